// round 11
// baseline (speedup 1.0000x reference)
#include <cuda_runtime.h>
#include <cuda_fp16.h>
#include <cstdint>

// EmbeddingBag(mode='sum') + bias — single fused persistent kernel.
//
// Model (validated over 6 rounds): runtime == total LTS bytes / ~6300 B/cyc
// chip cap. Bytes are at their floor (fp16 table gather, 252MB; sub-fp16
// fails the 1e-3 error budget). The only remaining cost was the ~0.7us
// inter-kernel launch gap, removed here by fusing:
//   phase 1: all CTAs convert fp32 table -> fp16 scratch (grid-stride)
//   barrier: grid-wide generation barrier (all CTAs co-resident: grid is
//            sized from cudaOccupancyMaxActiveBlocksPerMultiprocessor)
//   phase 2: warp-per-bag gather-sum (LDG.128 rows, fp16 tree-of-4 partial
//            sums, fp32 accumulate, bias init) — the proven 19.0us body.

#define HIDDEN   256
#define MAX_ROWS 6144
#define ROW_U4   32   // 256 halves = 512B = 32 uint4 per row

__device__ __half    g_table_h[MAX_ROWS * HIDDEN];  // 3 MB scratch
__device__ unsigned  g_arrive = 0;                  // barrier arrivals
__device__ unsigned  g_gen    = 0;                  // barrier generation

__device__ __forceinline__ unsigned h2_to_u(__half2 h) {
    unsigned u; memcpy(&u, &h, 4); return u;
}
__device__ __forceinline__ __half2 u_to_h2(unsigned u) {
    __half2 h; memcpy(&h, &u, 4); return h;
}

__device__ __forceinline__ void tree4_acc(float acc[8],
                                          const uint4& v0, const uint4& v1,
                                          const uint4& v2, const uint4& v3)
{
    __half2 s0 = __hadd2(__hadd2(u_to_h2(v0.x), u_to_h2(v1.x)),
                         __hadd2(u_to_h2(v2.x), u_to_h2(v3.x)));
    __half2 s1 = __hadd2(__hadd2(u_to_h2(v0.y), u_to_h2(v1.y)),
                         __hadd2(u_to_h2(v2.y), u_to_h2(v3.y)));
    __half2 s2 = __hadd2(__hadd2(u_to_h2(v0.z), u_to_h2(v1.z)),
                         __hadd2(u_to_h2(v2.z), u_to_h2(v3.z)));
    __half2 s3 = __hadd2(__hadd2(u_to_h2(v0.w), u_to_h2(v1.w)),
                         __hadd2(u_to_h2(v2.w), u_to_h2(v3.w)));
    float2 f0 = __half22float2(s0);
    float2 f1 = __half22float2(s1);
    float2 f2 = __half22float2(s2);
    float2 f3 = __half22float2(s3);
    acc[0] += f0.x; acc[1] += f0.y;
    acc[2] += f1.x; acc[3] += f1.y;
    acc[4] += f2.x; acc[5] += f2.y;
    acc[6] += f3.x; acc[7] += f3.y;
}

__device__ __forceinline__ void one_acc(float acc[8], const uint4& v)
{
    float2 f0 = __half22float2(u_to_h2(v.x));
    float2 f1 = __half22float2(u_to_h2(v.y));
    float2 f2 = __half22float2(u_to_h2(v.z));
    float2 f3 = __half22float2(u_to_h2(v.w));
    acc[0] += f0.x; acc[1] += f0.y;
    acc[2] += f1.x; acc[3] += f1.y;
    acc[4] += f2.x; acc[5] += f2.y;
    acc[6] += f3.x; acc[7] += f3.y;
}

__global__ __launch_bounds__(256)
void embag_fused_kernel(const int* __restrict__ idx,
                        const int* __restrict__ offs,
                        const float4* __restrict__ table4,
                        const float* __restrict__ bias,
                        float* __restrict__ out,
                        int batch, int n_total, int n8)
{
    // ---------------- phase 1: fp32 -> fp16 convert (grid-stride) ----------
    const int gtid    = blockIdx.x * blockDim.x + threadIdx.x;
    const int gthreads = gridDim.x * blockDim.x;
    for (int t = gtid; t < n8; t += gthreads) {
        float4 a = __ldg(table4 + 2 * t);
        float4 b = __ldg(table4 + 2 * t + 1);
        uint4 v;
        v.x = h2_to_u(__floats2half2_rn(a.x, a.y));
        v.y = h2_to_u(__floats2half2_rn(a.z, a.w));
        v.z = h2_to_u(__floats2half2_rn(b.x, b.y));
        v.w = h2_to_u(__floats2half2_rn(b.z, b.w));
        reinterpret_cast<uint4*>(g_table_h)[t] = v;
    }
    __threadfence();   // make fp16 table globally visible before barrier
    __syncthreads();

    // ---------------- grid-wide generation barrier -------------------------
    // Grid is sized so all CTAs are co-resident (occupancy query on host).
    // g_gen grows monotonically across graph replays: no reset hazard.
    if (threadIdx.x == 0) {
        const unsigned gen = atomicAdd(&g_gen, 0u);           // snapshot
        const unsigned ticket = atomicAdd(&g_arrive, 1u);
        if (ticket == gridDim.x - 1) {
            g_arrive = 0;                                     // ready for next replay
            __threadfence();
            atomicAdd(&g_gen, 1u);                            // release
        } else {
            while (atomicAdd(&g_gen, 0u) == gen) {
                __nanosleep(64);
            }
        }
    }
    __syncthreads();

    // ---------------- phase 2: warp-per-bag gather-sum ---------------------
    const int warp0   = gtid >> 5;
    const int lane    = threadIdx.x & 31;
    const int wstride = gthreads >> 5;
    const uint4* base = reinterpret_cast<const uint4*>(g_table_h) + lane;

    for (int bag = warp0; bag < batch; bag += wstride) {
        const int start = __ldg(offs + bag);
        const int end   = (bag + 1 < batch) ? __ldg(offs + bag + 1) : n_total;

        float acc[8];
        {
            float4 b0 = __ldg(reinterpret_cast<const float4*>(bias) + 2 * lane);
            float4 b1 = __ldg(reinterpret_cast<const float4*>(bias) + 2 * lane + 1);
            acc[0] = b0.x; acc[1] = b0.y; acc[2] = b0.z; acc[3] = b0.w;
            acc[4] = b1.x; acc[5] = b1.y; acc[6] = b1.z; acc[7] = b1.w;
        }

        int j = start;
        if (j + 4 <= end) {
            int i0 = __ldg(idx + j + 0);
            int i1 = __ldg(idx + j + 1);
            int i2 = __ldg(idx + j + 2);
            int i3 = __ldg(idx + j + 3);
            for (; j + 8 <= end; j += 4) {
                const int m0 = __ldg(idx + j + 4);
                const int m1 = __ldg(idx + j + 5);
                const int m2 = __ldg(idx + j + 6);
                const int m3 = __ldg(idx + j + 7);
                const uint4 v0 = base[(size_t)i0 * ROW_U4];
                const uint4 v1 = base[(size_t)i1 * ROW_U4];
                const uint4 v2 = base[(size_t)i2 * ROW_U4];
                const uint4 v3 = base[(size_t)i3 * ROW_U4];
                tree4_acc(acc, v0, v1, v2, v3);
                i0 = m0; i1 = m1; i2 = m2; i3 = m3;
            }
            const uint4 v0 = base[(size_t)i0 * ROW_U4];
            const uint4 v1 = base[(size_t)i1 * ROW_U4];
            const uint4 v2 = base[(size_t)i2 * ROW_U4];
            const uint4 v3 = base[(size_t)i3 * ROW_U4];
            tree4_acc(acc, v0, v1, v2, v3);
            j += 4;
        }
        for (; j < end; ++j) {
            const int i = __ldg(idx + j);
            one_acc(acc, base[(size_t)i * ROW_U4]);
        }

        float4* o = reinterpret_cast<float4*>(out + (size_t)bag * HIDDEN) + 2 * lane;
        o[0] = make_float4(acc[0], acc[1], acc[2], acc[3]);
        o[1] = make_float4(acc[4], acc[5], acc[6], acc[7]);
    }
}

extern "C" void kernel_launch(void* const* d_in, const int* in_sizes, int n_in,
                              void* d_out, int out_size)
{
    const int*    feature_indices = (const int*)d_in[0];
    const int*    offsets         = (const int*)d_in[1];
    const float4* table4          = (const float4*)d_in[2];
    const float*  bias            = (const float*)d_in[3];
    float*        out             = (float*)d_out;

    const int n_total     = in_sizes[0];
    const int batch       = in_sizes[1];
    const int table_elems = in_sizes[2];
    const int n8          = table_elems / 8;

    // Size grid for guaranteed co-residency (spin barrier requires all CTAs
    // resident in one wave). Pure host queries; deterministic.
    static int s_grid = 0;
    if (s_grid == 0) {
        int dev = 0, sms = 0, maxb = 0;
        cudaGetDevice(&dev);
        cudaDeviceGetAttribute(&sms, cudaDevAttrMultiProcessorCount, dev);
        cudaOccupancyMaxActiveBlocksPerMultiprocessor(&maxb, embag_fused_kernel,
                                                      256, 0);
        if (sms <= 0)  sms = 148;
        if (maxb <= 0) maxb = 1;
        s_grid = sms * maxb;
    }

    embag_fused_kernel<<<s_grid, 256>>>(feature_indices, offsets, table4, bias,
                                        out, batch, n_total, n8);
}